// round 3
// baseline (speedup 1.0000x reference)
#include <cuda_runtime.h>
#include <math.h>

#define N_NODES 100000
#define N_EDGES 6400000
#define F_IN    128
#define F_OUT   16

// ---------------- device scratch (no allocations allowed) ----------------
__device__ int   g_deg   [N_NODES];          // in-degree (excl. self loop)
__device__ int   g_off   [N_NODES + 1];      // CSR offsets
__device__ int   g_cursor[N_NODES];          // binning cursors
__device__ float g_dinv  [N_NODES];          // rsqrt(deg+1)
__device__ float g_g     [N_NODES * F_OUT];  // dinv[n] * (x[n] @ W)
__device__ int   g_sorted[N_EDGES];          // src ids sorted by dst

// ---------------- K0: reset (every call / graph replay) -------------------
__global__ void __launch_bounds__(256) k_init(float* __restrict__ out) {
    int i = blockIdx.x * blockDim.x + threadIdx.x;
    if (i < N_NODES) g_deg[i] = 0;
    if (i < F_OUT) out[i] = 0.0f;
}

// ---------------- K1: in-degree of target nodes ---------------------------
__global__ void __launch_bounds__(256) k_degree(const int* __restrict__ dst) {
    int e = blockIdx.x * blockDim.x + threadIdx.x;
    if (e < N_EDGES) atomicAdd(&g_deg[dst[e]], 1);
}

// ---------------- K2: exclusive scan -> off, cursor, dinv (1 CTA) ---------
__global__ void __launch_bounds__(1024) k_scan() {
    const int CH = 100;                       // 1024*100 >= N_NODES, 4-aligned
    __shared__ int warp_sums[32];
    int t = threadIdx.x;
    int lane = t & 31, wid = t >> 5;
    int base = t * CH;

    // pass 1: chunk sum (vectorized)
    int sum = 0;
    if (base < N_NODES) {
        const int4* d4 = (const int4*)(g_deg + base);
#pragma unroll
        for (int i = 0; i < CH / 4; i++) {
            int idx = base + i * 4;
            if (idx + 3 < N_NODES) {
                int4 v = d4[i];
                sum += v.x + v.y + v.z + v.w;
            } else {
                for (int j = 0; j < 4; j++)
                    if (idx + j < N_NODES) sum += g_deg[idx + j];
            }
        }
    }

    // block exclusive scan of per-thread sums
    int v = sum;
#pragma unroll
    for (int off = 1; off < 32; off <<= 1) {
        int u = __shfl_up_sync(0xFFFFFFFFu, v, off);
        if (lane >= off) v += u;
    }
    if (lane == 31) warp_sums[wid] = v;
    __syncthreads();
    if (wid == 0) {
        int w = warp_sums[lane];
#pragma unroll
        for (int off = 1; off < 32; off <<= 1) {
            int u = __shfl_up_sync(0xFFFFFFFFu, w, off);
            if (lane >= off) w += u;
        }
        warp_sums[lane] = w;                  // inclusive warp totals
    }
    __syncthreads();
    int excl = v - sum + (wid > 0 ? warp_sums[wid - 1] : 0);

    // pass 2: write running offsets, cursors, dinv
    int run = excl;
    for (int i = 0; i < CH; i++) {
        int idx = base + i;
        if (idx < N_NODES) {
            int d = g_deg[idx];
            g_off[idx] = run;
            g_cursor[idx] = run;
            g_dinv[idx] = rsqrtf((float)(d + 1));   // +1 self loop
            run += d;
        }
    }
    if (t == 1023) g_off[N_NODES] = run;       // == N_EDGES
}

// ---------------- K3: g[n] = dinv[n] * (x[n] @ W) --------------------------
__global__ void __launch_bounds__(128) k_gemm(const float* __restrict__ x,
                                              const float* __restrict__ W) {
    __shared__ float Ws[F_IN * F_OUT];
    for (int i = threadIdx.x; i < F_IN * F_OUT; i += blockDim.x) Ws[i] = W[i];
    __syncthreads();

    int n = blockIdx.x * blockDim.x + threadIdx.x;
    if (n >= N_NODES) return;

    const float4* x4 = (const float4*)(x + (size_t)n * F_IN);
    float acc[F_OUT];
#pragma unroll
    for (int f = 0; f < F_OUT; f++) acc[f] = 0.f;

#pragma unroll
    for (int k4 = 0; k4 < F_IN / 4; k4++) {
        float4 xv = x4[k4];
        int k = k4 * 4;
#pragma unroll
        for (int f = 0; f < F_OUT; f++) {
            acc[f] += xv.x * Ws[(k + 0) * F_OUT + f];
            acc[f] += xv.y * Ws[(k + 1) * F_OUT + f];
            acc[f] += xv.z * Ws[(k + 2) * F_OUT + f];
            acc[f] += xv.w * Ws[(k + 3) * F_OUT + f];
        }
    }
    float dinv = g_dinv[n];
    float4* gg = (float4*)(g_g + (size_t)n * F_OUT);
#pragma unroll
    for (int q = 0; q < 4; q++)
        gg[q] = make_float4(acc[q * 4 + 0] * dinv, acc[q * 4 + 1] * dinv,
                            acc[q * 4 + 2] * dinv, acc[q * 4 + 3] * dinv);
}

// ---------------- K4: counting-sort bin (src sorted by dst) ----------------
__global__ void __launch_bounds__(256) k_bin(const int* __restrict__ src,
                                             const int* __restrict__ dst) {
    int e = blockIdx.x * blockDim.x + threadIdx.x;
    if (e < N_EDGES) {
        int c = dst[e];
        int p = atomicAdd(&g_cursor[c], 1);
        g_sorted[p] = src[e];
    }
}

// ---------------- K5: per-node aggregate + tanh + mean pool ----------------
// 1024-thr CTA = 32 warps = 32 nodes; lane layout: slot = lane>>2 (8 edge
// slots), q = lane&3 (float4 feature quad). No float atomics on messages.
__global__ void __launch_bounds__(1024) k_aggfin(const float* __restrict__ b,
                                                 float* __restrict__ out) {
    __shared__ float red[32][F_OUT];
    int wid = threadIdx.x >> 5, lane = threadIdx.x & 31;
    int n = blockIdx.x * 32 + wid;             // exactly 100000 warps
    int q = lane & 3, slot = lane >> 2;

    const float4* G = (const float4*)g_g;
    float4 acc = make_float4(0.f, 0.f, 0.f, 0.f);

    int s0 = g_off[n], s1 = g_off[n + 1];
    for (int i = s0 + slot; i < s1; i += 8) {
        int s = g_sorted[i];                   // 4 lanes broadcast-load
        float4 v = G[s * 4 + q];               // 4 lanes cover 64B row
        acc.x += v.x; acc.y += v.y; acc.z += v.z; acc.w += v.w;
    }

    // reduce over the 8 slots (lane bits 2..4)
#pragma unroll
    for (int off = 16; off >= 4; off >>= 1) {
        acc.x += __shfl_xor_sync(0xFFFFFFFFu, acc.x, off);
        acc.y += __shfl_xor_sync(0xFFFFFFFFu, acc.y, off);
        acc.z += __shfl_xor_sync(0xFFFFFFFFu, acc.z, off);
        acc.w += __shfl_xor_sync(0xFFFFFFFFu, acc.w, off);
    }

    if (slot == 0) {
        float dv = g_dinv[n];
        float4 self = G[n * 4 + q];
        float4 bb = ((const float4*)b)[q];
        red[wid][q * 4 + 0] = tanhf(dv * (acc.x + self.x) + bb.x);
        red[wid][q * 4 + 1] = tanhf(dv * (acc.y + self.y) + bb.y);
        red[wid][q * 4 + 2] = tanhf(dv * (acc.z + self.z) + bb.z);
        red[wid][q * 4 + 3] = tanhf(dv * (acc.w + self.w) + bb.w);
    }
    __syncthreads();

    if (wid == 0 && lane < F_OUT) {
        float s = 0.f;
#pragma unroll
        for (int w = 0; w < 32; w++) s += red[w][lane];
        atomicAdd(&out[lane], s * (1.0f / (float)N_NODES));
    }
}

// ---------------- launch ---------------------------------------------------
extern "C" void kernel_launch(void* const* d_in, const int* in_sizes, int n_in,
                              void* d_out, int out_size) {
    const float* x  = (const float*)d_in[0];
    const int*   ei = (const int*)d_in[1];   // [2, N_EDGES] int32 (JAX x64 off)
    const float* W  = (const float*)d_in[2];
    const float* b  = (const float*)d_in[3];
    float*       out = (float*)d_out;

    const int* src = ei;
    const int* dst = ei + N_EDGES;

    k_init  <<<(N_NODES + 255) / 256, 256>>>(out);
    k_degree<<<(N_EDGES + 255) / 256, 256>>>(dst);
    k_scan  <<<1, 1024>>>();
    k_gemm  <<<(N_NODES + 127) / 128, 128>>>(x, W);
    k_bin   <<<(N_EDGES + 255) / 256, 256>>>(src, dst);
    k_aggfin<<<N_NODES / 32, 1024>>>(b, out);
}

// round 4
// speedup vs baseline: 1.6598x; 1.6598x over previous
#include <cuda_runtime.h>
#include <math.h>

#define N_NODES 100000
#define N_EDGES 6400000
#define F_IN    128
#define F_OUT   16

// ---------------- device scratch (no allocations; zero-initialized) -------
__device__ int   g_deg [N_NODES];            // in-deg; RESET to 0 by k_dinv
__device__ float g_dinv[N_NODES];            // rsqrt(deg+1)
__device__ float g_g   [N_NODES * F_OUT];    // h = x@W, then scaled by dinv
__device__ float g_acc [N_NODES * F_OUT];    // scatter acc; RESET by finalize

// Fused kernel A: blocks [0, GEMM_BLOCKS) compute h = x@W (4 threads/node,
// K-split); blocks [GEMM_BLOCKS, +DEG_BLOCKS) count in-degrees.
#define GEMM_BLOCKS 1563                     // 1563*256 >= 4*N_NODES
#define DEG_BLOCKS  25000                    // 25000*256 = N_EDGES

__global__ void __launch_bounds__(256) k_fusedA(const float* __restrict__ x,
                                                const float* __restrict__ W,
                                                const int* __restrict__ dst) {
    if (blockIdx.x < GEMM_BLOCKS) {
        __shared__ float Ws[F_IN * F_OUT];
        for (int i = threadIdx.x; i < F_IN * F_OUT; i += 256) Ws[i] = W[i];
        __syncthreads();

        int gt = blockIdx.x * 256 + threadIdx.x;
        int n = gt >> 2;                      // node
        int part = gt & 3;                    // K quarter: 32 floats
        if (n >= N_NODES) return;

        const float4* x4 = (const float4*)(x + (size_t)n * F_IN) + part * 8;
        float acc[F_OUT];
#pragma unroll
        for (int f = 0; f < F_OUT; f++) acc[f] = 0.f;

#pragma unroll
        for (int k4 = 0; k4 < 8; k4++) {
            float4 xv = x4[k4];
            int k = part * 32 + k4 * 4;
#pragma unroll
            for (int f = 0; f < F_OUT; f++) {
                acc[f] += xv.x * Ws[(k + 0) * F_OUT + f];
                acc[f] += xv.y * Ws[(k + 1) * F_OUT + f];
                acc[f] += xv.z * Ws[(k + 2) * F_OUT + f];
                acc[f] += xv.w * Ws[(k + 3) * F_OUT + f];
            }
        }
        // combine the 4 K-partials (lanes n*4..n*4+3 are adjacent)
#pragma unroll
        for (int f = 0; f < F_OUT; f++) {
            acc[f] += __shfl_xor_sync(0xFFFFFFFFu, acc[f], 1);
            acc[f] += __shfl_xor_sync(0xFFFFFFFFu, acc[f], 2);
        }
        if (part == 0) {
            float4* gg = (float4*)(g_g + (size_t)n * F_OUT);
#pragma unroll
            for (int q = 0; q < 4; q++)
                gg[q] = make_float4(acc[q * 4 + 0], acc[q * 4 + 1],
                                    acc[q * 4 + 2], acc[q * 4 + 3]);
        }
    } else {
        int e = (blockIdx.x - GEMM_BLOCKS) * 256 + threadIdx.x;
        if (e < N_EDGES) atomicAdd(&g_deg[dst[e]], 1);
    }
}

// k_dinv: dinv = rsqrt(deg+1); g *= dinv; reset deg; zero out.
__global__ void __launch_bounds__(256) k_dinv(float* __restrict__ out) {
    int n = blockIdx.x * 256 + threadIdx.x;
    if (n < N_NODES) {
        float dv = rsqrtf((float)(g_deg[n] + 1));
        g_dinv[n] = dv;
        g_deg[n] = 0;                          // restore invariant for replay
        float4* gg = (float4*)(g_g + (size_t)n * F_OUT);
#pragma unroll
        for (int q = 0; q < 4; q++) {
            float4 v = gg[q];
            gg[q] = make_float4(v.x * dv, v.y * dv, v.z * dv, v.w * dv);
        }
    }
    if (n < F_OUT) out[n] = 0.0f;
}

// k_scatter: acc[dst] += g[src]  (4 threads per edge, vector RED)
__global__ void __launch_bounds__(256) k_scatter(const int* __restrict__ src,
                                                 const int* __restrict__ dst) {
    long long t = (long long)blockIdx.x * 256 + threadIdx.x;
    int e = (int)(t >> 2);
    int q = (int)(t & 3);
    if (e >= N_EDGES) return;
    int r = src[e];
    int c = dst[e];
    float4 v = ((const float4*)g_g)[r * 4 + q];
    float* p = g_acc + (size_t)c * F_OUT + q * 4;
    asm volatile("red.global.add.v4.f32 [%0], {%1,%2,%3,%4};"
                 :: "l"(p), "f"(v.x), "f"(v.y), "f"(v.z), "f"(v.w)
                 : "memory");
}

// k_finalize: out = mean_n tanh(dinv*(acc+g) + b); then zero acc.
__global__ void __launch_bounds__(256) k_finalize(const float* __restrict__ b,
                                                  float* __restrict__ out) {
    float bb[F_OUT];
#pragma unroll
    for (int f = 0; f < F_OUT; f++) bb[f] = b[f];

    float local[F_OUT];
#pragma unroll
    for (int f = 0; f < F_OUT; f++) local[f] = 0.f;

    const float4 z4 = make_float4(0.f, 0.f, 0.f, 0.f);
    for (int n = blockIdx.x * 256 + threadIdx.x; n < N_NODES;
         n += gridDim.x * 256) {
        float dv = g_dinv[n];
        float4* a4 = (float4*)(g_acc + (size_t)n * F_OUT);
        const float4* g4 = (const float4*)(g_g + (size_t)n * F_OUT);
#pragma unroll
        for (int q = 0; q < 4; q++) {
            float4 a = a4[q];
            float4 g = g4[q];
            a4[q] = z4;                        // restore invariant for replay
            local[q * 4 + 0] += tanhf(dv * (a.x + g.x) + bb[q * 4 + 0]);
            local[q * 4 + 1] += tanhf(dv * (a.y + g.y) + bb[q * 4 + 1]);
            local[q * 4 + 2] += tanhf(dv * (a.z + g.z) + bb[q * 4 + 2]);
            local[q * 4 + 3] += tanhf(dv * (a.w + g.w) + bb[q * 4 + 3]);
        }
    }

#pragma unroll
    for (int off = 16; off > 0; off >>= 1) {
#pragma unroll
        for (int f = 0; f < F_OUT; f++)
            local[f] += __shfl_xor_sync(0xFFFFFFFFu, local[f], off);
    }
    if ((threadIdx.x & 31) < F_OUT) {
        atomicAdd(&out[threadIdx.x & 31],
                  local[threadIdx.x & 31] * (1.0f / (float)N_NODES));
    }
}

// ---------------- launch ---------------------------------------------------
extern "C" void kernel_launch(void* const* d_in, const int* in_sizes, int n_in,
                              void* d_out, int out_size) {
    const float* x  = (const float*)d_in[0];
    const int*   ei = (const int*)d_in[1];   // [2, N_EDGES] int32 (JAX x64 off)
    const float* W  = (const float*)d_in[2];
    const float* b  = (const float*)d_in[3];
    float*       out = (float*)d_out;

    const int* src = ei;
    const int* dst = ei + N_EDGES;

    k_fusedA  <<<GEMM_BLOCKS + DEG_BLOCKS, 256>>>(x, W, dst);
    k_dinv    <<<(N_NODES + 255) / 256, 256>>>(out);
    {
        long long threads = (long long)N_EDGES * 4;
        k_scatter<<<(int)((threads + 255) / 256), 256>>>(src, dst);
    }
    k_finalize<<<592, 256>>>(b, out);
}